// round 14
// baseline (speedup 1.0000x reference)
#include <cuda_runtime.h>
#include <cuda_fp16.h>
#include <cstdint>
#include <math.h>

// ---------------------------------------------------------------------------
// MoE FFN: N=8192, D=1024, H=4096, E=8, top-2.
// router -> scan -> build -> HMMA fp16 grouped GEMM1(+GELU) -> GEMM2 ->
// gated combine.  Module = EXACTLY the R10 kernel set that passed all harness
// memory checks (7 kernels, no prep/convert kernels, fp32 weights packed to
// fp16 inside the gemm loaders).  Deltas vs R10, confined to gemm_hmma:
//   1. GEMM1 grid roles swapped (M fast) -> consecutive CTAs share the same
//      weight panel in L2; x (32 MB) takes the scattered-reuse role instead.
//   2. Triple-buffered smem, prefetch distance 2 (same register lifetime,
//      same load/store idioms as R10).
// ---------------------------------------------------------------------------

#define NTOK   8192
#define DDIM   1024
#define HDIM   4096
#define NEXP   8
#define NASSIGN (NTOK * 2)

// ------------------------- device scratch ----------------------------------
__device__ int   g_counts[NEXP];
__device__ int   g_offsets[NEXP];
__device__ int   g_cursor[NEXP];
__device__ int   g_tok_e[NASSIGN];
__device__ float g_tok_g[NASSIGN];
__device__ int   g_tok_pos[NASSIGN];
__device__ int   g_perm[NASSIGN];
__device__ __align__(128) __half g_h[(size_t)NASSIGN * HDIM];   // 128 MB
__device__ __align__(128) float  g_y[(size_t)NASSIGN * DDIM];   // 64 MB

// ------------------------- helpers -----------------------------------------
__device__ __forceinline__ float gelu_fast(float x) {
    float u = 0.7978845608028654f * x * (1.0f + 0.044715f * x * x);
    float t;
    asm("tanh.approx.f32 %0, %1;" : "=f"(t) : "f"(u));
    return 0.5f * x * (1.0f + t);
}

__device__ __forceinline__ unsigned pack_h2(float lo, float hi) {
    unsigned ulo = (unsigned)__half_as_ushort(__float2half_rn(lo));
    unsigned uhi = (unsigned)__half_as_ushort(__float2half_rn(hi));
    return ulo | (uhi << 16);
}

#define MMA_F16(c, a0, a1, a2, a3, b0, b1) \
    asm volatile( \
        "mma.sync.aligned.m16n8k16.row.col.f32.f16.f16.f32 " \
        "{%0,%1,%2,%3}, {%4,%5,%6,%7}, {%8,%9}, {%0,%1,%2,%3};\n" \
        : "+f"((c)[0]), "+f"((c)[1]), "+f"((c)[2]), "+f"((c)[3]) \
        : "r"(a0), "r"(a1), "r"(a2), "r"(a3), "r"(b0), "r"(b1))

// ------------------------- small kernels (verbatim from R10) ---------------
__global__ void init_kernel() {
    if (threadIdx.x < NEXP) g_counts[threadIdx.x] = 0;
}

__global__ __launch_bounds__(256) void router_kernel(
    const float* __restrict__ x, const float* __restrict__ rw, const float* __restrict__ rb)
{
    __shared__ float s_rw[DDIM * NEXP];
    for (int i = threadIdx.x; i < DDIM * NEXP; i += 256) s_rw[i] = rw[i];
    __syncthreads();
    int warp = threadIdx.x >> 5, lane = threadIdx.x & 31;
    int tok  = blockIdx.x * 8 + warp;
    const float* xr = x + (size_t)tok * DDIM;
    float acc[NEXP];
#pragma unroll
    for (int e = 0; e < NEXP; e++) acc[e] = 0.0f;
    for (int i = lane; i < DDIM; i += 32) {
        float xv = xr[i];
        const float* r = s_rw + i * NEXP;
#pragma unroll
        for (int e = 0; e < NEXP; e++) acc[e] += xv * r[e];
    }
#pragma unroll
    for (int off = 16; off > 0; off >>= 1)
#pragma unroll
        for (int e = 0; e < NEXP; e++)
            acc[e] += __shfl_xor_sync(0xFFFFFFFFu, acc[e], off);
    if (lane == 0) {
        float lg[NEXP];
#pragma unroll
        for (int e = 0; e < NEXP; e++) lg[e] = acc[e] + rb[e];
        int i0 = 0;
#pragma unroll
        for (int e = 1; e < NEXP; e++) if (lg[e] > lg[i0]) i0 = e;
        int i1 = -1;
#pragma unroll
        for (int e = 0; e < NEXP; e++) {
            if (e == i0) continue;
            if (i1 < 0 || lg[e] > lg[i1]) i1 = e;
        }
        float d  = lg[i1] - lg[i0];
        float g0 = 1.0f / (1.0f + expf(d));
        g_tok_e[2 * tok] = i0;  g_tok_e[2 * tok + 1] = i1;
        g_tok_g[2 * tok] = g0;  g_tok_g[2 * tok + 1] = 1.0f - g0;
        atomicAdd(&g_counts[i0], 1);
        atomicAdd(&g_counts[i1], 1);
    }
}

__global__ void scan_kernel() {
    if (threadIdx.x == 0) {
        int s = 0;
        for (int e = 0; e < NEXP; e++) { g_offsets[e] = s; g_cursor[e] = s; s += g_counts[e]; }
    }
}

__global__ void build_kernel() {
    int tok = blockIdx.x * blockDim.x + threadIdx.x;
    if (tok >= NTOK) return;
#pragma unroll
    for (int k = 0; k < 2; k++) {
        int e = g_tok_e[2 * tok + k];
        int pos = atomicAdd(&g_cursor[e], 1);
        g_perm[pos] = tok;
        g_tok_pos[2 * tok + k] = pos;
    }
}

// ------------------------- fp16 HMMA grouped GEMM --------------------------
// C[cnt,NDIM] = A[cnt,KDIM] @ W[e][KDIM,NDIM]   (W in natural [K][N] layout)
// block tile 128x128x16, 256 threads (8 warps, warp tile 64x32).
// Triple-buffered smem, prefetch distance 2.  PHASE1 maps M to blockIdx.x
// (consecutive CTAs share the weight panel in L2); PHASE2 keeps N fast.
#define BM 128
#define BN 128
#define BK 16
#define PA 12
#define PB 136

template<int KDIM, bool PHASE1>
__global__ __launch_bounds__(256) void gemm_hmma(
    const float* __restrict__ Ain,      // PHASE1: x (fp32); PHASE2 unused
    const float* __restrict__ Wbase,    // w1 / w2 (fp32, [E][K][N])
    const float* __restrict__ biasBase) // b1 (PHASE1 only)
{
    const int NDIM = PHASE1 ? HDIM : DDIM;
    int e = blockIdx.z;
    int cnt = g_counts[e];
    int m0, n0;
    if (PHASE1) { m0 = blockIdx.x * BM; n0 = blockIdx.y * BN; }
    else        { m0 = blockIdx.y * BM; n0 = blockIdx.x * BN; }
    if (m0 >= cnt) return;
    int off = g_offsets[e];

    const float* W = Wbase + (size_t)e * KDIM * NDIM;

    __shared__ __align__(16) __half2 sA[3][BM][PA];       // [m][k2]; 18432 B
    __shared__ __align__(16) __half2 sB[3][BK / 2][PB];   // [k2][n]; 13056 B

    int t = threadIdx.x, lane = t & 31, warp = t >> 5;
    int wr = warp >> 2, wc = warp & 3;
    int gid = lane >> 2, t4 = lane & 3;

    // ---- A loader (verbatim R10): 2 chunks/thread = (row, 4 consecutive k)
    int aR0 = t >> 2,          aC0 = (t & 3) << 2;
    int aR1 = (t + 256) >> 2,  aC1 = ((t + 256) & 3) << 2;
    size_t aOfs0, aOfs1;
    {
        int gr0 = m0 + aR0; if (gr0 >= cnt) gr0 = cnt - 1;
        int gr1 = m0 + aR1; if (gr1 >= cnt) gr1 = cnt - 1;
        int s0 = PHASE1 ? g_perm[off + gr0] : (off + gr0);
        int s1 = PHASE1 ? g_perm[off + gr1] : (off + gr1);
        aOfs0 = (size_t)s0 * KDIM + aC0;
        aOfs1 = (size_t)s1 * KDIM + aC1;
    }
    // ---- B loader (verbatim R10): rows {2kp,2kp+1} x 4 consecutive n ------
    int kp  = t >> 5;                  // 0..7
    int bn4 = lane << 2;               // 0..124
    size_t bOfs = (size_t)(2 * kp) * NDIM + n0 + bn4;

    const int KT = KDIM / BK;

    // ---- prefetch registers (verbatim R10 idioms) ----
    float4 av0, av1, bv0, bv1;
    uint2  ah0, ah1;

    // ---- preamble: fill buffers 0 and 1 ----
#pragma unroll
    for (int p = 0; p < 2; p++) {
        int k16 = p * BK;
        if (PHASE1) {
            av0 = *(const float4*)(Ain + aOfs0 + k16);
            av1 = *(const float4*)(Ain + aOfs1 + k16);
        } else {
            ah0 = *(const uint2*)(g_h + aOfs0 + k16);
            ah1 = *(const uint2*)(g_h + aOfs1 + k16);
        }
        bv0 = *(const float4*)(W + bOfs + (size_t)k16 * NDIM);
        bv1 = *(const float4*)(W + bOfs + (size_t)k16 * NDIM + NDIM);
        if (PHASE1) {
            uint2 pa0 = make_uint2(pack_h2(av0.x, av0.y), pack_h2(av0.z, av0.w));
            uint2 pa1 = make_uint2(pack_h2(av1.x, av1.y), pack_h2(av1.z, av1.w));
            *(uint2*)&sA[p][aR0][aC0 >> 1] = pa0;
            *(uint2*)&sA[p][aR1][aC1 >> 1] = pa1;
        } else {
            *(uint2*)&sA[p][aR0][aC0 >> 1] = ah0;
            *(uint2*)&sA[p][aR1][aC1 >> 1] = ah1;
        }
        uint4 pb = make_uint4(pack_h2(bv0.x, bv1.x), pack_h2(bv0.y, bv1.y),
                              pack_h2(bv0.z, bv1.z), pack_h2(bv0.w, bv1.w));
        *(uint4*)&sB[p][kp][bn4] = pb;
    }
    __syncthreads();

    float acc[4][4][4] = {};
    int buf = 0;          // buffer holding slab kt
    int nxt = 2;          // buffer to fill with slab kt+2

    for (int kt = 0; kt < KT; ++kt) {
        // issue loads for slab kt+2 (prefetch distance 2)
        if (kt + 2 < KT) {
            int k16 = (kt + 2) * BK;
            if (PHASE1) {
                av0 = *(const float4*)(Ain + aOfs0 + k16);
                av1 = *(const float4*)(Ain + aOfs1 + k16);
            } else {
                ah0 = *(const uint2*)(g_h + aOfs0 + k16);
                ah1 = *(const uint2*)(g_h + aOfs1 + k16);
            }
            bv0 = *(const float4*)(W + bOfs + (size_t)k16 * NDIM);
            bv1 = *(const float4*)(W + bOfs + (size_t)k16 * NDIM + NDIM);
        }

        // fragments + 16 HMMA (one k16 slice per stage) -- verbatim R10
        unsigned A0[4], A1[4], A2[4], A3[4];
#pragma unroll
        for (int mt = 0; mt < 4; mt++) {
            int row = wr * 64 + mt * 16;
            A0[mt] = *(const unsigned*)&sA[buf][row + gid    ][t4    ];
            A1[mt] = *(const unsigned*)&sA[buf][row + gid + 8][t4    ];
            A2[mt] = *(const unsigned*)&sA[buf][row + gid    ][t4 + 4];
            A3[mt] = *(const unsigned*)&sA[buf][row + gid + 8][t4 + 4];
        }
        unsigned B0[4], B1[4];
#pragma unroll
        for (int nt = 0; nt < 4; nt++) {
            int col = wc * 32 + nt * 8 + gid;
            B0[nt] = *(const unsigned*)&sB[buf][t4    ][col];
            B1[nt] = *(const unsigned*)&sB[buf][t4 + 4][col];
        }
#pragma unroll
        for (int mt = 0; mt < 4; mt++)
#pragma unroll
            for (int nt = 0; nt < 4; nt++)
                MMA_F16(acc[mt][nt], A0[mt], A1[mt], A2[mt], A3[mt], B0[nt], B1[nt]);

        // store slab kt+2 into the buffer consumed at kt-1 -- verbatim idioms
        if (kt + 2 < KT) {
            if (PHASE1) {
                uint2 pa0 = make_uint2(pack_h2(av0.x, av0.y), pack_h2(av0.z, av0.w));
                uint2 pa1 = make_uint2(pack_h2(av1.x, av1.y), pack_h2(av1.z, av1.w));
                *(uint2*)&sA[nxt][aR0][aC0 >> 1] = pa0;
                *(uint2*)&sA[nxt][aR1][aC1 >> 1] = pa1;
            } else {
                *(uint2*)&sA[nxt][aR0][aC0 >> 1] = ah0;
                *(uint2*)&sA[nxt][aR1][aC1 >> 1] = ah1;
            }
            uint4 pb = make_uint4(pack_h2(bv0.x, bv1.x), pack_h2(bv0.y, bv1.y),
                                  pack_h2(bv0.z, bv1.z), pack_h2(bv0.w, bv1.w));
            *(uint4*)&sB[nxt][kp][bn4] = pb;
        }
        __syncthreads();
        buf = buf + 1; if (buf == 3) buf = 0;
        nxt = nxt + 1; if (nxt == 3) nxt = 0;
    }

    // ---- epilogue (verbatim R10) ----
#pragma unroll
    for (int nt = 0; nt < 4; nt++) {
        int colg = n0 + wc * 32 + nt * 8 + t4 * 2;
        float bv0e = 0.0f, bv1e = 0.0f;
        if (PHASE1) {
            bv0e = __ldg(biasBase + (size_t)e * HDIM + colg);
            bv1e = __ldg(biasBase + (size_t)e * HDIM + colg + 1);
        }
#pragma unroll
        for (int mt = 0; mt < 4; mt++) {
            int r0e = m0 + wr * 64 + mt * 16 + gid;
            int r1e = r0e + 8;
            if (PHASE1) {
                if (r0e < cnt) {
                    float h0 = gelu_fast(acc[mt][nt][0] + bv0e);
                    float h1 = gelu_fast(acc[mt][nt][1] + bv1e);
                    *(__half2*)(g_h + (size_t)(off + r0e) * HDIM + colg) =
                        __floats2half2_rn(h0, h1);
                }
                if (r1e < cnt) {
                    float h0 = gelu_fast(acc[mt][nt][2] + bv0e);
                    float h1 = gelu_fast(acc[mt][nt][3] + bv1e);
                    *(__half2*)(g_h + (size_t)(off + r1e) * HDIM + colg) =
                        __floats2half2_rn(h0, h1);
                }
            } else {
                if (r0e < cnt) {
                    float2 v = make_float2(acc[mt][nt][0], acc[mt][nt][1]);
                    *(float2*)(g_y + (size_t)(off + r0e) * DDIM + colg) = v;
                }
                if (r1e < cnt) {
                    float2 v = make_float2(acc[mt][nt][2], acc[mt][nt][3]);
                    *(float2*)(g_y + (size_t)(off + r1e) * DDIM + colg) = v;
                }
            }
        }
    }
}

// ------------------------- combine (verbatim from R10) ---------------------
__global__ __launch_bounds__(256) void combine_kernel(
    const float* __restrict__ b2, float* __restrict__ out)
{
    int tok = blockIdx.x;
    int e0 = g_tok_e[2 * tok], e1 = g_tok_e[2 * tok + 1];
    float gg0 = g_tok_g[2 * tok], gg1 = g_tok_g[2 * tok + 1];
    int p0 = g_tok_pos[2 * tok], p1 = g_tok_pos[2 * tok + 1];
    int j = threadIdx.x * 4;
    float4 y0 = *(const float4*)(g_y + (size_t)p0 * DDIM + j);
    float4 y1 = *(const float4*)(g_y + (size_t)p1 * DDIM + j);
    float4 b0 = *(const float4*)(b2 + (size_t)e0 * DDIM + j);
    float4 b1v = *(const float4*)(b2 + (size_t)e1 * DDIM + j);
    float4 o;
    o.x = gg0 * (y0.x + b0.x) + gg1 * (y1.x + b1v.x);
    o.y = gg0 * (y0.y + b0.y) + gg1 * (y1.y + b1v.y);
    o.z = gg0 * (y0.z + b0.z) + gg1 * (y1.z + b1v.z);
    o.w = gg0 * (y0.w + b0.w) + gg1 * (y1.w + b1v.w);
    *(float4*)(out + (size_t)tok * DDIM + j) = o;
}

// ------------------------- launch ------------------------------------------
extern "C" void kernel_launch(void* const* d_in, const int* in_sizes, int n_in,
                              void* d_out, int out_size) {
    const float* x  = (const float*)d_in[0];
    const float* rw = (const float*)d_in[1];
    const float* rb = (const float*)d_in[2];
    const float* w1 = (const float*)d_in[3];
    const float* b1 = (const float*)d_in[4];
    const float* w2 = (const float*)d_in[5];
    const float* b2 = (const float*)d_in[6];
    float* out = (float*)d_out;

    init_kernel<<<1, 32>>>();
    router_kernel<<<NTOK / 8, 256>>>(x, rw, rb);
    scan_kernel<<<1, 32>>>();
    build_kernel<<<(NTOK + 255) / 256, 256>>>();

    // GEMM1: M fast in grid.x (weight-panel L2 reuse); -> gelu -> g_h (fp16)
    gemm_hmma<DDIM, true ><<<dim3(NASSIGN / BM, HDIM / BN, NEXP), 256>>>(x, w1, b1);
    // GEMM2: N fast in grid.x (g_h-panel L2 reuse); -> g_y (fp32)
    gemm_hmma<HDIM, false><<<dim3(DDIM / BN, NASSIGN / BM, NEXP), 256>>>(x, w2, b1);

    combine_kernel<<<NTOK, 256>>>(b2, out);
}

// round 15
// speedup vs baseline: 1.0224x; 1.0224x over previous
#include <cuda_runtime.h>
#include <cuda_fp16.h>
#include <cstdint>
#include <math.h>

// ---------------------------------------------------------------------------
// MoE FFN: N=8192, D=1024, H=4096, E=8, top-2.
// router -> scan -> build -> HMMA fp16 grouped GEMM1(+GELU) -> GEMM2 ->
// gated combine.  Module = EXACTLY the R10 kernel set that passed all harness
// memory checks.  Single delta vs R10, confined to gemm_hmma: BK=32 (half the
// syncs, 8 independent LDG.128 per thread per slab) using R10 loader idioms
// duplicated.  Grid order and double buffering as in R10.
// ---------------------------------------------------------------------------

#define NTOK   8192
#define DDIM   1024
#define HDIM   4096
#define NEXP   8
#define NASSIGN (NTOK * 2)

// ------------------------- device scratch ----------------------------------
__device__ int   g_counts[NEXP];
__device__ int   g_offsets[NEXP];
__device__ int   g_cursor[NEXP];
__device__ int   g_tok_e[NASSIGN];
__device__ float g_tok_g[NASSIGN];
__device__ int   g_tok_pos[NASSIGN];
__device__ int   g_perm[NASSIGN];
__device__ __align__(128) __half g_h[(size_t)NASSIGN * HDIM];   // 128 MB
__device__ __align__(128) float  g_y[(size_t)NASSIGN * DDIM];   // 64 MB

// ------------------------- helpers -----------------------------------------
__device__ __forceinline__ float gelu_fast(float x) {
    float u = 0.7978845608028654f * x * (1.0f + 0.044715f * x * x);
    float t;
    asm("tanh.approx.f32 %0, %1;" : "=f"(t) : "f"(u));
    return 0.5f * x * (1.0f + t);
}

__device__ __forceinline__ unsigned pack_h2(float lo, float hi) {
    unsigned ulo = (unsigned)__half_as_ushort(__float2half_rn(lo));
    unsigned uhi = (unsigned)__half_as_ushort(__float2half_rn(hi));
    return ulo | (uhi << 16);
}

#define MMA_F16(c, a0, a1, a2, a3, b0, b1) \
    asm volatile( \
        "mma.sync.aligned.m16n8k16.row.col.f32.f16.f16.f32 " \
        "{%0,%1,%2,%3}, {%4,%5,%6,%7}, {%8,%9}, {%0,%1,%2,%3};\n" \
        : "+f"((c)[0]), "+f"((c)[1]), "+f"((c)[2]), "+f"((c)[3]) \
        : "r"(a0), "r"(a1), "r"(a2), "r"(a3), "r"(b0), "r"(b1))

// ------------------------- small kernels (verbatim from R10) ---------------
__global__ void init_kernel() {
    if (threadIdx.x < NEXP) g_counts[threadIdx.x] = 0;
}

__global__ __launch_bounds__(256) void router_kernel(
    const float* __restrict__ x, const float* __restrict__ rw, const float* __restrict__ rb)
{
    __shared__ float s_rw[DDIM * NEXP];
    for (int i = threadIdx.x; i < DDIM * NEXP; i += 256) s_rw[i] = rw[i];
    __syncthreads();
    int warp = threadIdx.x >> 5, lane = threadIdx.x & 31;
    int tok  = blockIdx.x * 8 + warp;
    const float* xr = x + (size_t)tok * DDIM;
    float acc[NEXP];
#pragma unroll
    for (int e = 0; e < NEXP; e++) acc[e] = 0.0f;
    for (int i = lane; i < DDIM; i += 32) {
        float xv = xr[i];
        const float* r = s_rw + i * NEXP;
#pragma unroll
        for (int e = 0; e < NEXP; e++) acc[e] += xv * r[e];
    }
#pragma unroll
    for (int off = 16; off > 0; off >>= 1)
#pragma unroll
        for (int e = 0; e < NEXP; e++)
            acc[e] += __shfl_xor_sync(0xFFFFFFFFu, acc[e], off);
    if (lane == 0) {
        float lg[NEXP];
#pragma unroll
        for (int e = 0; e < NEXP; e++) lg[e] = acc[e] + rb[e];
        int i0 = 0;
#pragma unroll
        for (int e = 1; e < NEXP; e++) if (lg[e] > lg[i0]) i0 = e;
        int i1 = -1;
#pragma unroll
        for (int e = 0; e < NEXP; e++) {
            if (e == i0) continue;
            if (i1 < 0 || lg[e] > lg[i1]) i1 = e;
        }
        float d  = lg[i1] - lg[i0];
        float g0 = 1.0f / (1.0f + expf(d));
        g_tok_e[2 * tok] = i0;  g_tok_e[2 * tok + 1] = i1;
        g_tok_g[2 * tok] = g0;  g_tok_g[2 * tok + 1] = 1.0f - g0;
        atomicAdd(&g_counts[i0], 1);
        atomicAdd(&g_counts[i1], 1);
    }
}

__global__ void scan_kernel() {
    if (threadIdx.x == 0) {
        int s = 0;
        for (int e = 0; e < NEXP; e++) { g_offsets[e] = s; g_cursor[e] = s; s += g_counts[e]; }
    }
}

__global__ void build_kernel() {
    int tok = blockIdx.x * blockDim.x + threadIdx.x;
    if (tok >= NTOK) return;
#pragma unroll
    for (int k = 0; k < 2; k++) {
        int e = g_tok_e[2 * tok + k];
        int pos = atomicAdd(&g_cursor[e], 1);
        g_perm[pos] = tok;
        g_tok_pos[2 * tok + k] = pos;
    }
}

// ------------------------- fp16 HMMA grouped GEMM --------------------------
// C[cnt,NDIM] = A[cnt,KDIM] @ W[e][KDIM,NDIM]   (W in natural [K][N] layout)
// block tile 128x128x32, 256 threads (8 warps, warp tile 64x32), double buffer
// smem: sA[m][k2] half2 (PA2=20), sB[k2][n] half2 (PB=136); 26.1 KB static.
#define BM 128
#define BN 128
#define BK 32
#define PA2 20
#define PB 136

template<int KDIM, bool PHASE1>
__global__ __launch_bounds__(256) void gemm_hmma(
    const float* __restrict__ Ain,      // PHASE1: x (fp32); PHASE2 unused
    const float* __restrict__ Wbase,    // w1 / w2 (fp32, [E][K][N])
    const float* __restrict__ biasBase) // b1 (PHASE1 only)
{
    const int NDIM = PHASE1 ? HDIM : DDIM;
    int e = blockIdx.z;
    int cnt = g_counts[e];
    int m0 = blockIdx.y * BM;
    if (m0 >= cnt) return;
    int off = g_offsets[e];
    int n0 = blockIdx.x * BN;

    const float* W = Wbase + (size_t)e * KDIM * NDIM;

    __shared__ __align__(16) __half2 sA[2][BM][PA2];      // [m][k2]; 20480 B
    __shared__ __align__(16) __half2 sB[2][BK / 2][PB];   // [k2][n]; 17408 B

    int t = threadIdx.x, lane = t & 31, warp = t >> 5;
    int wr = warp >> 2, wc = warp & 3;
    int gid = lane >> 2, t4 = lane & 3;

    // ---- A loader: 4 chunks/thread; chunk ci=(t+i*256): row ci>>3,
    //      4 consecutive k at (ci&7)*4  (extends R10's 2-chunk scheme)
    int aR0 = t >> 3, aC0 = (t & 7) << 2;    // rows aR0, +32, +64, +96
    size_t aOfs0, aOfs1, aOfs2, aOfs3;
    {
        int gr0 = m0 + aR0;      if (gr0 >= cnt) gr0 = cnt - 1;
        int gr1 = m0 + aR0 + 32; if (gr1 >= cnt) gr1 = cnt - 1;
        int gr2 = m0 + aR0 + 64; if (gr2 >= cnt) gr2 = cnt - 1;
        int gr3 = m0 + aR0 + 96; if (gr3 >= cnt) gr3 = cnt - 1;
        int s0 = PHASE1 ? g_perm[off + gr0] : (off + gr0);
        int s1 = PHASE1 ? g_perm[off + gr1] : (off + gr1);
        int s2 = PHASE1 ? g_perm[off + gr2] : (off + gr2);
        int s3 = PHASE1 ? g_perm[off + gr3] : (off + gr3);
        aOfs0 = (size_t)s0 * KDIM + aC0;
        aOfs1 = (size_t)s1 * KDIM + aC0;
        aOfs2 = (size_t)s2 * KDIM + aC0;
        aOfs3 = (size_t)s3 * KDIM + aC0;
    }
    // ---- B loader (R10 scheme x2): rows {2kp,2kp+1} and {16+2kp,16+2kp+1}
    int kp  = t >> 5;                  // 0..7
    int bn4 = lane << 2;               // 0..124
    size_t bOfs  = (size_t)(2 * kp) * NDIM + n0 + bn4;
    size_t bOfsH = bOfs + (size_t)16 * NDIM;

    const int KT = KDIM / BK;

    // ---- prefetch registers (R10 idioms) ----
    float4 av0, av1, av2, av3, bv0, bv1, bv2, bv3;
    uint2  ah0, ah1, ah2, ah3;
    if (PHASE1) {
        av0 = *(const float4*)(Ain + aOfs0);
        av1 = *(const float4*)(Ain + aOfs1);
        av2 = *(const float4*)(Ain + aOfs2);
        av3 = *(const float4*)(Ain + aOfs3);
    } else {
        ah0 = *(const uint2*)(g_h + aOfs0);
        ah1 = *(const uint2*)(g_h + aOfs1);
        ah2 = *(const uint2*)(g_h + aOfs2);
        ah3 = *(const uint2*)(g_h + aOfs3);
    }
    bv0 = *(const float4*)(W + bOfs);
    bv1 = *(const float4*)(W + bOfs + NDIM);
    bv2 = *(const float4*)(W + bOfsH);
    bv3 = *(const float4*)(W + bOfsH + NDIM);

    // ---- store stage 0 ----
    {
        if (PHASE1) {
            uint2 pa0 = make_uint2(pack_h2(av0.x, av0.y), pack_h2(av0.z, av0.w));
            uint2 pa1 = make_uint2(pack_h2(av1.x, av1.y), pack_h2(av1.z, av1.w));
            uint2 pa2 = make_uint2(pack_h2(av2.x, av2.y), pack_h2(av2.z, av2.w));
            uint2 pa3 = make_uint2(pack_h2(av3.x, av3.y), pack_h2(av3.z, av3.w));
            *(uint2*)&sA[0][aR0     ][aC0 >> 1] = pa0;
            *(uint2*)&sA[0][aR0 + 32][aC0 >> 1] = pa1;
            *(uint2*)&sA[0][aR0 + 64][aC0 >> 1] = pa2;
            *(uint2*)&sA[0][aR0 + 96][aC0 >> 1] = pa3;
        } else {
            *(uint2*)&sA[0][aR0     ][aC0 >> 1] = ah0;
            *(uint2*)&sA[0][aR0 + 32][aC0 >> 1] = ah1;
            *(uint2*)&sA[0][aR0 + 64][aC0 >> 1] = ah2;
            *(uint2*)&sA[0][aR0 + 96][aC0 >> 1] = ah3;
        }
        uint4 pb0 = make_uint4(pack_h2(bv0.x, bv1.x), pack_h2(bv0.y, bv1.y),
                               pack_h2(bv0.z, bv1.z), pack_h2(bv0.w, bv1.w));
        uint4 pb1 = make_uint4(pack_h2(bv2.x, bv3.x), pack_h2(bv2.y, bv3.y),
                               pack_h2(bv2.z, bv3.z), pack_h2(bv2.w, bv3.w));
        *(uint4*)&sB[0][kp    ][bn4] = pb0;
        *(uint4*)&sB[0][kp + 8][bn4] = pb1;
    }
    __syncthreads();

    float acc[4][4][4] = {};
    int buf = 0;

    for (int kt = 0; kt < KT; ++kt) {
        // prefetch next 32-K slab
        if (kt + 1 < KT) {
            int k32 = (kt + 1) * BK;
            if (PHASE1) {
                av0 = *(const float4*)(Ain + aOfs0 + k32);
                av1 = *(const float4*)(Ain + aOfs1 + k32);
                av2 = *(const float4*)(Ain + aOfs2 + k32);
                av3 = *(const float4*)(Ain + aOfs3 + k32);
            } else {
                ah0 = *(const uint2*)(g_h + aOfs0 + k32);
                ah1 = *(const uint2*)(g_h + aOfs1 + k32);
                ah2 = *(const uint2*)(g_h + aOfs2 + k32);
                ah3 = *(const uint2*)(g_h + aOfs3 + k32);
            }
            bv0 = *(const float4*)(W + bOfs  + (size_t)k32 * NDIM);
            bv1 = *(const float4*)(W + bOfs  + (size_t)k32 * NDIM + NDIM);
            bv2 = *(const float4*)(W + bOfsH + (size_t)k32 * NDIM);
            bv3 = *(const float4*)(W + bOfsH + (size_t)k32 * NDIM + NDIM);
        }

        // two k16 slices per slab (frag reads + 16 HMMA each, R10 idioms)
#pragma unroll
        for (int ks = 0; ks < 2; ks++) {
            int kc = ks * 8;
            unsigned A0[4], A1[4], A2[4], A3[4];
#pragma unroll
            for (int mt = 0; mt < 4; mt++) {
                int row = wr * 64 + mt * 16;
                A0[mt] = *(const unsigned*)&sA[buf][row + gid    ][kc + t4    ];
                A1[mt] = *(const unsigned*)&sA[buf][row + gid + 8][kc + t4    ];
                A2[mt] = *(const unsigned*)&sA[buf][row + gid    ][kc + t4 + 4];
                A3[mt] = *(const unsigned*)&sA[buf][row + gid + 8][kc + t4 + 4];
            }
            unsigned B0[4], B1[4];
#pragma unroll
            for (int nt = 0; nt < 4; nt++) {
                int col = wc * 32 + nt * 8 + gid;
                B0[nt] = *(const unsigned*)&sB[buf][kc + t4    ][col];
                B1[nt] = *(const unsigned*)&sB[buf][kc + t4 + 4][col];
            }
#pragma unroll
            for (int mt = 0; mt < 4; mt++)
#pragma unroll
                for (int nt = 0; nt < 4; nt++)
                    MMA_F16(acc[mt][nt], A0[mt], A1[mt], A2[mt], A3[mt],
                            B0[nt], B1[nt]);
        }

        // store next stage
        if (kt + 1 < KT) {
            int nb = buf ^ 1;
            if (PHASE1) {
                uint2 pa0 = make_uint2(pack_h2(av0.x, av0.y), pack_h2(av0.z, av0.w));
                uint2 pa1 = make_uint2(pack_h2(av1.x, av1.y), pack_h2(av1.z, av1.w));
                uint2 pa2 = make_uint2(pack_h2(av2.x, av2.y), pack_h2(av2.z, av2.w));
                uint2 pa3 = make_uint2(pack_h2(av3.x, av3.y), pack_h2(av3.z, av3.w));
                *(uint2*)&sA[nb][aR0     ][aC0 >> 1] = pa0;
                *(uint2*)&sA[nb][aR0 + 32][aC0 >> 1] = pa1;
                *(uint2*)&sA[nb][aR0 + 64][aC0 >> 1] = pa2;
                *(uint2*)&sA[nb][aR0 + 96][aC0 >> 1] = pa3;
            } else {
                *(uint2*)&sA[nb][aR0     ][aC0 >> 1] = ah0;
                *(uint2*)&sA[nb][aR0 + 32][aC0 >> 1] = ah1;
                *(uint2*)&sA[nb][aR0 + 64][aC0 >> 1] = ah2;
                *(uint2*)&sA[nb][aR0 + 96][aC0 >> 1] = ah3;
            }
            uint4 pb0 = make_uint4(pack_h2(bv0.x, bv1.x), pack_h2(bv0.y, bv1.y),
                                   pack_h2(bv0.z, bv1.z), pack_h2(bv0.w, bv1.w));
            uint4 pb1 = make_uint4(pack_h2(bv2.x, bv3.x), pack_h2(bv2.y, bv3.y),
                                   pack_h2(bv2.z, bv3.z), pack_h2(bv2.w, bv3.w));
            *(uint4*)&sB[nb][kp    ][bn4] = pb0;
            *(uint4*)&sB[nb][kp + 8][bn4] = pb1;
        }
        __syncthreads();
        buf ^= 1;
    }

    // ---- epilogue (verbatim R10) ----
#pragma unroll
    for (int nt = 0; nt < 4; nt++) {
        int colg = n0 + wc * 32 + nt * 8 + t4 * 2;
        float bv0e = 0.0f, bv1e = 0.0f;
        if (PHASE1) {
            bv0e = __ldg(biasBase + (size_t)e * HDIM + colg);
            bv1e = __ldg(biasBase + (size_t)e * HDIM + colg + 1);
        }
#pragma unroll
        for (int mt = 0; mt < 4; mt++) {
            int r0e = m0 + wr * 64 + mt * 16 + gid;
            int r1e = r0e + 8;
            if (PHASE1) {
                if (r0e < cnt) {
                    float h0 = gelu_fast(acc[mt][nt][0] + bv0e);
                    float h1 = gelu_fast(acc[mt][nt][1] + bv1e);
                    *(__half2*)(g_h + (size_t)(off + r0e) * HDIM + colg) =
                        __floats2half2_rn(h0, h1);
                }
                if (r1e < cnt) {
                    float h0 = gelu_fast(acc[mt][nt][2] + bv0e);
                    float h1 = gelu_fast(acc[mt][nt][3] + bv1e);
                    *(__half2*)(g_h + (size_t)(off + r1e) * HDIM + colg) =
                        __floats2half2_rn(h0, h1);
                }
            } else {
                if (r0e < cnt) {
                    float2 v = make_float2(acc[mt][nt][0], acc[mt][nt][1]);
                    *(float2*)(g_y + (size_t)(off + r0e) * DDIM + colg) = v;
                }
                if (r1e < cnt) {
                    float2 v = make_float2(acc[mt][nt][2], acc[mt][nt][3]);
                    *(float2*)(g_y + (size_t)(off + r1e) * DDIM + colg) = v;
                }
            }
        }
    }
}

// ------------------------- combine (verbatim from R10) ---------------------
__global__ __launch_bounds__(256) void combine_kernel(
    const float* __restrict__ b2, float* __restrict__ out)
{
    int tok = blockIdx.x;
    int e0 = g_tok_e[2 * tok], e1 = g_tok_e[2 * tok + 1];
    float gg0 = g_tok_g[2 * tok], gg1 = g_tok_g[2 * tok + 1];
    int p0 = g_tok_pos[2 * tok], p1 = g_tok_pos[2 * tok + 1];
    int j = threadIdx.x * 4;
    float4 y0 = *(const float4*)(g_y + (size_t)p0 * DDIM + j);
    float4 y1 = *(const float4*)(g_y + (size_t)p1 * DDIM + j);
    float4 b0 = *(const float4*)(b2 + (size_t)e0 * DDIM + j);
    float4 b1v = *(const float4*)(b2 + (size_t)e1 * DDIM + j);
    float4 o;
    o.x = gg0 * (y0.x + b0.x) + gg1 * (y1.x + b1v.x);
    o.y = gg0 * (y0.y + b0.y) + gg1 * (y1.y + b1v.y);
    o.z = gg0 * (y0.z + b0.z) + gg1 * (y1.z + b1v.z);
    o.w = gg0 * (y0.w + b0.w) + gg1 * (y1.w + b1v.w);
    *(float4*)(out + (size_t)tok * DDIM + j) = o;
}

// ------------------------- launch ------------------------------------------
extern "C" void kernel_launch(void* const* d_in, const int* in_sizes, int n_in,
                              void* d_out, int out_size) {
    const float* x  = (const float*)d_in[0];
    const float* rw = (const float*)d_in[1];
    const float* rb = (const float*)d_in[2];
    const float* w1 = (const float*)d_in[3];
    const float* b1 = (const float*)d_in[4];
    const float* w2 = (const float*)d_in[5];
    const float* b2 = (const float*)d_in[6];
    float* out = (float*)d_out;

    init_kernel<<<1, 32>>>();
    router_kernel<<<NTOK / 8, 256>>>(x, rw, rb);
    scan_kernel<<<1, 32>>>();
    build_kernel<<<(NTOK + 255) / 256, 256>>>();

    // GEMM1: [cnt,1024] @ [1024,4096] -> gelu -> g_h (fp16)
    gemm_hmma<DDIM, true ><<<dim3(HDIM / BN, NASSIGN / BM, NEXP), 256>>>(x, w1, b1);
    // GEMM2: [cnt,4096] @ [4096,1024] -> g_y (fp32)
    gemm_hmma<HDIM, false><<<dim3(DDIM / BN, NASSIGN / BM, NEXP), 256>>>(x, w2, b1);

    combine_kernel<<<NTOK, 256>>>(b2, out);
}